// round 7
// baseline (speedup 1.0000x reference)
#include <cuda_runtime.h>
#include <cuda_bf16.h>

// Problem: MultinomialCELoss
//   x: [N=8, Q=441, H=128, W=128] f32, y: [N=8, 2, H=128, W=128] f32
//   out[w] = -sum_{n,h} log( x[n, idx(n,h,w), h, w] )
//
// R6b: same theory as R6 (pin the replay-invariant 17MB gathered line set in
// L2 so steady-state graph replays dodge the random-128B DRAM wall), but with
// the ptxas-accepted encoding: createpolicy.fractional.L2::evict_last +
// ld.global.nc.L2::cache_hint (scalar evict_last modifier is rejected on
// sm_103a). Structure: R1's 8-gathers-per-thread batching, fused single
// kernel, slice-padded REDG accumulators, fence+arrival-counter tail.

#define N_  8
#define Q_  441
#define H_  128
#define W_  128
#define HW_ (H_ * W_)
#define NBINS 21
#define PAD 64                 // 256B stride: spreads 128 accs across L2 slices
#define GRID H_                // 128 CTAs, one per h
#define TPB  W_                // 128 threads, one per w

__device__ float g_acc[W_ * PAD];   // zero-initialized at module load
__device__ unsigned int g_count;    // zero-initialized at module load

__device__ __forceinline__ int ab_bin(float v) {
    // Match JAX f32 semantics: floor((v + 110) / 10), clipped to [0,20].
    // __fdiv_rn keeps IEEE division even under fast-math (bin boundaries).
    float q = floorf(__fdiv_rn(v + 110.0f, 10.0f));
    int qi = (int)q;
    qi = qi < 0 ? 0 : qi;
    qi = qi > (NBINS - 1) ? (NBINS - 1) : qi;
    return qi;
}

__device__ __forceinline__ float ldg_evict_last(const float* p) {
    float v;
    asm volatile(
        "{\n\t"
        ".reg .b64 pol;\n\t"
        "createpolicy.fractional.L2::evict_last.b64 pol, 1.0;\n\t"
        "ld.global.nc.L2::cache_hint.f32 %0, [%1], pol;\n\t"
        "}"
        : "=f"(v) : "l"(p));
    return v;
}

__global__ __launch_bounds__(TPB) void mce_fused_kernel(
    const float* __restrict__ x,
    const float* __restrict__ y,
    float* __restrict__ out)
{
    const int w = threadIdx.x;   // 0..127
    const int h = blockIdx.x;    // 0..127
    const int hw = h * W_ + w;

    // Stage all 16 y loads + index math first, then fire all 8 scattered
    // gathers back-to-back (8 outstanding DRAM/L2 chains per thread).
    int idx[N_];
    #pragma unroll
    for (int n = 0; n < N_; n++) {
        float ya = ldg_evict_last(&y[(size_t)(n * 2 + 0) * HW_ + hw]);
        float yb = ldg_evict_last(&y[(size_t)(n * 2 + 1) * HW_ + hw]);
        idx[n] = ab_bin(ya) * NBINS + ab_bin(yb);
    }

    float v[N_];
    #pragma unroll
    for (int n = 0; n < N_; n++) {
        // evict_last hint: keep the gathered lines resident in L2 so
        // steady-state graph replays hit L2 instead of random DRAM.
        v[n] = ldg_evict_last(&x[((size_t)n * Q_ + idx[n]) * HW_ + hw]);
    }

    float acc = 0.0f;
    #pragma unroll
    for (int n = 0; n < N_; n++) acc += logf(v[n]);

    // Fire-and-forget REDG into slice-padded accumulator.
    atomicAdd(&g_acc[w * PAD], acc);

    __threadfence();
    __syncthreads();

    __shared__ unsigned int s_last;
    if (w == 0) {
        s_last = (atomicAdd(&g_count, 1u) == GRID - 1) ? 1u : 0u;
    }
    __syncthreads();

    if (s_last) {
        __threadfence();                 // order acc reads after counter obs
        float s = g_acc[w * PAD];
        out[w] = -s;
        g_acc[w * PAD] = 0.0f;           // restore zero state for next replay
        if (w == 0) g_count = 0u;
    }
}

extern "C" void kernel_launch(void* const* d_in, const int* in_sizes, int n_in,
                              void* d_out, int out_size) {
    const float* x = (const float*)d_in[0];
    const float* y = (const float*)d_in[1];
    float* out = (float*)d_out;

    mce_fused_kernel<<<GRID, TPB>>>(x, y, out);
}

// round 8
// speedup vs baseline: 1.2353x; 1.2353x over previous
#include <cuda_runtime.h>
#include <cuda_bf16.h>

// Problem: MultinomialCELoss
//   x: [N=8, Q=441, H=128, W=128] f32, y: [N=8, 2, H=128, W=128] f32
//   out[w] = -sum_{n,h} log( x[n, idx(n,h,w), h, w] )
//
// R8: strip ALL synchronization off the critical path. Evidence: the bare
// gather profiles at 1.9us (R3); every fence/counter tail variant costs
// 2-4us extra (R5/R7); fire-and-forget beats fenced. So: kernel A does the
// gathers and writes one plain coalesced partial per thread (no atomics, no
// fences, no zero-init — scratch fully overwritten each replay); kernel B
// (1 CTA) reduces 128 partials per w. __logf (MUFU.LG2) shortens the serial
// tail; error ~2^-21 << 1e-3 tolerance.

#define N_  8
#define Q_  441
#define H_  128
#define W_  128
#define HW_ (H_ * W_)
#define NBINS 21
#define GRIDA 128            // one CTA per 8-row group; 128 SMs active
#define TPB   128            // one thread per w

__device__ float g_partial[GRIDA * W_];   // 64 KB scratch, overwritten each run

__device__ __forceinline__ int ab_bin(float v) {
    // Match JAX f32 semantics: floor((v + 110) / 10), clipped to [0,20].
    // __fdiv_rn keeps IEEE division even under fast-math (bin boundaries).
    float q = floorf(__fdiv_rn(v + 110.0f, 10.0f));
    int qi = (int)q;
    qi = qi < 0 ? 0 : qi;
    qi = qi > (NBINS - 1) ? (NBINS - 1) : qi;
    return qi;
}

// Kernel A: CTA b handles rows [8b, 8b+8) of the flattened (n,h) dimension.
// Thread w: 16 coalesced y loads -> 8 batched scattered gathers (MLP=8)
// -> 8 MUFU logs -> 1 coalesced store. No smem, no atomics, no fences.
__global__ __launch_bounds__(TPB) void mce_gather_kernel(
    const float* __restrict__ x,
    const float* __restrict__ y,
    float* __restrict__ partial)
{
    const int w = threadIdx.x;
    const int b = blockIdx.x;

    int idx[8];
    int n_[8], hw_[8];
    #pragma unroll
    for (int k = 0; k < 8; k++) {
        const int row = b * 8 + k;       // (n,h) flattened
        const int n = row >> 7;
        const int h = row & (H_ - 1);
        n_[k] = n;
        hw_[k] = h * W_ + w;
        float ya = y[(size_t)(n * 2 + 0) * HW_ + hw_[k]];
        float yb = y[(size_t)(n * 2 + 1) * HW_ + hw_[k]];
        idx[k] = ab_bin(ya) * NBINS + ab_bin(yb);
    }

    float v[8];
    #pragma unroll
    for (int k = 0; k < 8; k++) {
        v[k] = x[((size_t)n_[k] * Q_ + idx[k]) * HW_ + hw_[k]];
    }

    float acc = 0.0f;
    #pragma unroll
    for (int k = 0; k < 8; k++) acc += __logf(v[k]);

    partial[b * W_ + w] = acc;           // plain coalesced store
}

// Kernel B: one CTA, 1024 threads = (w, j) with j in [0,8).
// Thread (w,j) sums partials b = 16j..16j+15 (coalesced across w),
// smem-reduces the 8 j-partials per w, writes out[w] = -sum.
__global__ __launch_bounds__(1024) void mce_reduce_kernel(
    const float* __restrict__ partial,
    float* __restrict__ out)
{
    const int w = threadIdx.x & (W_ - 1);
    const int j = threadIdx.x >> 7;      // 0..7

    float a0 = 0.f, a1 = 0.f;
    #pragma unroll
    for (int i = 0; i < 16; i += 2) {
        a0 += partial[(j * 16 + i + 0) * W_ + w];
        a1 += partial[(j * 16 + i + 1) * W_ + w];
    }
    float acc = a0 + a1;

    __shared__ float red[8][W_];
    red[j][w] = acc;
    __syncthreads();

    if (j == 0) {
        float s = 0.f;
        #pragma unroll
        for (int i = 0; i < 8; i++) s += red[i][w];
        out[w] = -s;
    }
}

extern "C" void kernel_launch(void* const* d_in, const int* in_sizes, int n_in,
                              void* d_out, int out_size) {
    const float* x = (const float*)d_in[0];
    const float* y = (const float*)d_in[1];
    float* out = (float*)d_out;

    float* partial = nullptr;
    cudaGetSymbolAddress((void**)&partial, g_partial);

    mce_gather_kernel<<<GRIDA, TPB>>>(x, y, partial);
    mce_reduce_kernel<<<1, 1024>>>(partial, out);
}